// round 14
// baseline (speedup 1.0000x reference)
#include <cuda_runtime.h>
#include <cstdint>

// GraphRefiner: 256 graphs x (N=2000, F=2), shared sparse adjacency (E=7998).
// TAGConv(2->64,K=3) -> relu -> TAGConv(64->2,K=3) + residual.
// A (node-space) commutes with W (feature-space): layer-2 Horner'd in F=2 space.
// One CTA per graph, node state in SMEM, 2 CTAs/SM.
// R9: degree-sorted node processing. R10: closed-form build.
// R12: paired-node propagation (2 equal-degree nodes per thread -> 4 chains,
// half the serial iterations); norms stored pre-duplicated (LDG.64, no pack).

#define NNODES 2000
#define EMAX   8192
#define TPB    256
#define BTPB   1024

typedef unsigned long long ull;

// ---- persistent device scratch ----
__device__ unsigned       g_meta[2048];     // per sorted position: start|deg<<13|node<<20
__device__ unsigned short g_ssrc16[EMAX];   // sorted-order edge sources
__device__ ull            g_norm2[EMAX];    // sorted-order edge norms, duplicated (n,n)

// ======================= build (1 block) =====================================
__global__ void k_build(const int* __restrict__ row, const int* __restrict__ col,
                        const float* __restrict__ ew, int E) {
    extern __shared__ char bsm[];
    int*            hist  = (int*)bsm;                        // 2048 (counts -> cursors)
    int*            rp    = hist + 2048;                      // 2048 inclusive rowptr
    float*          dinv  = (float*)(rp + 2048);              // 2048
    unsigned short* ssrc  = (unsigned short*)(dinv + 2048);   // 8192 u16
    float*          sew   = (float*)(ssrc + 8192);            // 8192 f32
    unsigned char*  degA  = (unsigned char*)(sew + 8192);     // 2048
    int*            degc  = (int*)(degA + 2048);              // 128 bin counts
    int*            nodestart = degc + 128;                   // 128
    int*            ebinstart = nodestart + 128;              // 128
    int*            degcur    = ebinstart + 128;              // 128
    int*            wsum      = degcur + 128;                 // 32

    int tid  = threadIdx.x;
    int lane = tid & 31;
    int wid  = tid >> 5;

    hist[tid] = 0; hist[tid + BTPB] = 0;
    if (tid < 128) { degc[tid] = 0; degcur[tid] = 0; }
    __syncthreads();

    for (int e = tid; e < E; e += BTPB) atomicAdd(&hist[col[e]], 1);
    __syncthreads();

    // ---- hierarchical inclusive scan of hist[2048] -> rp ----
    {
        int a = hist[2 * tid], b = hist[2 * tid + 1];
        int s = a + b;
        #pragma unroll
        for (int off = 1; off < 32; off <<= 1) {
            int v = __shfl_up_sync(0xffffffffu, s, off);
            if (lane >= off) s += v;
        }
        if (lane == 31) wsum[wid] = s;
        __syncthreads();
        if (wid == 0) {
            int t = wsum[lane];
            #pragma unroll
            for (int off = 1; off < 32; off <<= 1) {
                int v = __shfl_up_sync(0xffffffffu, t, off);
                if (lane >= off) t += v;
            }
            wsum[lane] = t;
        }
        __syncthreads();
        int base = wid ? wsum[wid - 1] : 0;
        int incl = base + s;
        rp[2 * tid]     = incl - b;
        rp[2 * tid + 1] = incl;
        __syncthreads();
        hist[2 * tid]     = incl - b - a;   // exclusive cursor
        hist[2 * tid + 1] = incl - b;
    }
    __syncthreads();

    // fill CSR slots (order nondeterministic; canonical sort below fixes values)
    for (int e = tid; e < E; e += BTPB) {
        int c = col[e];
        int p = atomicAdd(&hist[c], 1);
        ssrc[p] = (unsigned short)row[e];
        sew[p]  = ew[e];
    }
    __syncthreads();

    // canonical per-node order (sort by (src, ew-bits)) + dinv + degree
    for (int n = tid; n < NNODES; n += BTPB) {
        int s = n ? rp[n - 1] : 0;
        int e = rp[n];
        for (int i = s + 1; i < e; ++i) {
            unsigned short ks = ssrc[i];
            float kw = sew[i];
            unsigned kb = __float_as_uint(kw);
            int j = i - 1;
            while (j >= s) {
                unsigned short js = ssrc[j];
                if (js > ks || (js == ks && __float_as_uint(sew[j]) > kb)) {
                    ssrc[j + 1] = js; sew[j + 1] = sew[j]; --j;
                } else break;
            }
            ssrc[j + 1] = ks; sew[j + 1] = kw;
        }
        float w = 0.f;
        for (int i = s; i < e; ++i) w += sew[i];
        dinv[n] = (w > 0.f) ? rsqrtf(w) : 0.f;
        int d = e - s;
        degA[n] = (unsigned char)d;
        atomicAdd(&degc[d], 1);
    }
    __syncthreads();

    // 128-bin exclusive scans (node positions and edge starts) by warp 0
    if (wid == 0) {
        int c0 = degc[4 * lane], c1 = degc[4 * lane + 1];
        int c2 = degc[4 * lane + 2], c3 = degc[4 * lane + 3];
        int sn = c0 + c1 + c2 + c3;
        int se = c0 * (4 * lane) + c1 * (4 * lane + 1) + c2 * (4 * lane + 2) + c3 * (4 * lane + 3);
        int isn = sn, ise = se;
        #pragma unroll
        for (int off = 1; off < 32; off <<= 1) {
            int v0 = __shfl_up_sync(0xffffffffu, isn, off);
            int v1 = __shfl_up_sync(0xffffffffu, ise, off);
            if (lane >= off) { isn += v0; ise += v1; }
        }
        int bn = isn - sn, be = ise - se;
        #pragma unroll
        for (int k = 0; k < 4; ++k) {
            int d = 4 * lane + k;
            int c = (k == 0) ? c0 : (k == 1) ? c1 : (k == 2) ? c2 : c3;
            nodestart[d] = bn;  ebinstart[d] = be;
            bn += c;            be += c * d;
        }
    }
    __syncthreads();

    // emit: position within degree bin via atomic (FP values stay deterministic)
    for (int n = tid; n < NNODES; n += BTPB) {
        int d = degA[n];
        int r = atomicAdd(&degcur[d], 1);
        int pos   = nodestart[d] + r;
        int start = ebinstart[d] + r * d;
        g_meta[pos] = (unsigned)start | ((unsigned)d << 13) | ((unsigned)n << 20);
        int sc = n ? rp[n - 1] : 0;
        float di = dinv[n];
        for (int j = 0; j < d; ++j) {
            int ss = ssrc[sc + j];
            g_ssrc16[start + j] = (unsigned short)ss;
            unsigned nb = __float_as_uint(di * sew[sc + j] * dinv[ss]);
            g_norm2[start + j] = (ull)nb | ((ull)nb << 32);
        }
    }
}
#define BUILD_SMEM ((2048 + 2048 + 2048) * 4 + 8192 * 2 + 8192 * 4 + 2048 + (128 * 4 + 32) * 4)

// ======================= main fused kernel ===================================

__device__ __forceinline__ ull pack2(float x, float y) {
    ull r; asm("mov.b64 %0, {%1, %2};" : "=l"(r) : "f"(x), "f"(y)); return r;
}
__device__ __forceinline__ void unpack2(ull v, float& x, float& y) {
    asm("mov.b64 {%0, %1}, %2;" : "=f"(x), "=f"(y) : "l"(v));
}
__device__ __forceinline__ void ffma2(ull& d, ull a, ull b) {
    asm("fma.rn.f32x2 %0, %1, %2, %0;" : "+l"(d) : "l"(a), "l"(b));
}
__device__ __forceinline__ ull add2(ull a, ull b) {
    ull r; asm("add.rn.f32x2 %0, %1, %2;" : "=l"(r) : "l"(a), "l"(b)); return r;
}

// SMEM layout (bytes); 16B-aligned blocks
#define SM_BUF    0                        // 4 x ull[NNODES] = 64000
#define SM_WTS    (4 * NNODES * 8)         // 544 ull = 4352
#define SM_META   (SM_WTS + 4352)          // u32[2000] = 8000
#define SM_SRC    (SM_META + 8000)         // u16[8192] = 16384
#define SM_TOTAL  (SM_SRC + EMAX * 2)      // 92736 -> 2 CTAs/SM

// paired-node propagation: thread owns sorted positions (2t, 2t+1); chain
// assignment by edge parity (even->chain0, odd->chain1) in both roles, so each
// node's sum is bitwise identical regardless of partner -> deterministic.
__device__ __forceinline__ void propagate(const ull* __restrict__ src,
                                          ull* __restrict__ dst,
                                          const unsigned* __restrict__ meta,
                                          const unsigned short* __restrict__ ssrc,
                                          bool accum, int tid) {
    #pragma unroll 1
    for (int pos = tid * 2; pos < NNODES; pos += TPB * 2) {
        unsigned mv0 = meta[pos];
        unsigned mv1 = meta[pos + 1];
        int st0 = (int)(mv0 & 8191u), d0 = (int)((mv0 >> 13) & 127u), n0 = (int)(mv0 >> 20);
        int st1 = (int)(mv1 & 8191u), d1 = (int)((mv1 >> 13) & 127u), n1 = (int)(mv1 >> 20);
        ull p0 = accum ? dst[n0] : 0ull;
        ull p1 = accum ? dst[n1] : 0ull;
        ull a00 = 0, a01 = 0, a10 = 0, a11 = 0;
        int jc = d0 & ~1;           // d0 <= d1 (degree-ascending positions)
        int j = 0;
        for (; j < jc; j += 2) {    // both nodes, 2 edges each: 4 chains
            ull w00 = __ldg(&g_norm2[st0 + j]);
            ull w01 = __ldg(&g_norm2[st0 + j + 1]);
            ull w10 = __ldg(&g_norm2[st1 + j]);
            ull w11 = __ldg(&g_norm2[st1 + j + 1]);
            ull v00 = src[ssrc[st0 + j]];
            ull v01 = src[ssrc[st0 + j + 1]];
            ull v10 = src[ssrc[st1 + j]];
            ull v11 = src[ssrc[st1 + j + 1]];
            ffma2(a00, w00, v00);
            ffma2(a01, w01, v01);
            ffma2(a10, w10, v10);
            ffma2(a11, w11, v11);
        }
        if (d0 & 1) {               // node0 odd tail (edge index jc: even -> chain0)
            ull w = __ldg(&g_norm2[st0 + jc]);
            ffma2(a00, w, src[ssrc[st0 + jc]]);
        }
        for (; j + 2 <= d1; j += 2) {   // node1 remainder, pairs
            ull w10 = __ldg(&g_norm2[st1 + j]);
            ull w11 = __ldg(&g_norm2[st1 + j + 1]);
            ull v10 = src[ssrc[st1 + j]];
            ull v11 = src[ssrc[st1 + j + 1]];
            ffma2(a10, w10, v10);
            ffma2(a11, w11, v11);
        }
        if (j < d1) {               // node1 odd tail (even index -> chain0)
            ull w = __ldg(&g_norm2[st1 + j]);
            ffma2(a10, w, src[ssrc[st1 + j]]);
        }
        dst[n0] = add2(add2(a00, a01), p0);
        dst[n1] = add2(add2(a10, a11), p1);
    }
}

extern __shared__ char smem[];

__global__ void __launch_bounds__(TPB, 2) k6_main(
    const float* __restrict__ x,
    const float* __restrict__ W1, const float* __restrict__ b1,
    const float* __restrict__ W2, const float* __restrict__ b2,
    float* __restrict__ out)
{
    ull* B0  = (ull*)(smem + SM_BUF);
    ull* B1v = B0 + NNODES;
    ull* B2v = B1v + NNODES;
    ull* B3v = B2v + NNODES;
    ull* wts = (ull*)(smem + SM_WTS);
    unsigned* meta = (unsigned*)(smem + SM_META);
    unsigned short* ssrc = (unsigned short*)(smem + SM_SRC);

    int tid = threadIdx.x;
    int g   = blockIdx.x;

    // ---- stage inputs ----
    const ulonglong2* xg2 = (const ulonglong2*)(x + (size_t)g * (2 * NNODES));
    ulonglong2* B02 = (ulonglong2*)B0;
    for (int i = tid; i < NNODES / 2; i += TPB) B02[i] = xg2[i];

    // weights packed per tile t (J=4): [w1t:16][w2t:16][b1t:2] = 34 ull
    {
        const ull* w1u = (const ull*)W1;
        const ull* w2u = (const ull*)W2;
        const ull* b1u = (const ull*)b1;
        for (int idx = tid; idx < 16 * 34; idx += TPB) {
            int t = idx / 34, r = idx % 34;
            ull v;
            if (r < 16)      { int i = r >> 1, d = r & 1; v = w1u[i * 32 + 2 * t + d]; }
            else if (r < 32) { int rr = r - 16; int j = rr >> 2, q = rr & 3; v = w2u[q * 64 + 4 * t + j]; }
            else             { v = b1u[2 * t + (r - 32)]; }
            wts[idx] = v;
        }
    }
    for (int i = tid; i < NNODES; i += TPB) meta[i] = g_meta[i];
    {
        unsigned* s32 = (unsigned*)ssrc;
        const unsigned* g32 = (const unsigned*)g_ssrc16;
        for (int i = tid; i < EMAX / 2; i += TPB) s32[i] = g32[i];
    }
    ull b2p = pack2(b2[0], b2[1]);
    __syncthreads();

    // ---- layer-1 hops: z1..z3 ----
    propagate(B0,  B1v, meta, ssrc, false, tid); __syncthreads();
    propagate(B1v, B2v, meta, ssrc, false, tid); __syncthreads();
    propagate(B2v, B3v, meta, ssrc, false, tid); __syncthreads();

    // ---- dense phase: z in regs across tiles; w1/w2 phase-split ----
    #pragma unroll 1
    for (int strip = 0; strip < 2; ++strip) {
        int nb = tid + strip * 1024;
        ull z[16];
        #pragma unroll
        for (int m = 0; m < 4; ++m) {
            int n = nb + (m << 8);
            if (n >= NNODES) n = 0;              // dummy; write suppressed later
            z[m * 4 + 0] = B0[n];  z[m * 4 + 1] = B1v[n];
            z[m * 4 + 2] = B2v[n]; z[m * 4 + 3] = B3v[n];
        }
        ull y[16];
        #pragma unroll
        for (int c = 0; c < 16; ++c) y[c] = 0ull;

        #pragma unroll 1
        for (int t = 0; t < 16; ++t) {
            const ulonglong2* wq = (const ulonglong2*)(wts + t * 34);
            ull w[16], h[8];
            #pragma unroll
            for (int c = 0; c < 8; ++c) { ulonglong2 u = wq[c]; w[2*c] = u.x; w[2*c+1] = u.y; }
            ulonglong2 ub = wq[16];
            #pragma unroll
            for (int m = 0; m < 4; ++m) {
                ull h0 = ub.x, h1 = ub.y;
                #pragma unroll
                for (int r = 0; r < 4; ++r) {
                    float za, zb; unpack2(z[m * 4 + r], za, zb);
                    ull bza = pack2(za, za), bzb = pack2(zb, zb);
                    ffma2(h0, bza, w[(2 * r) * 2]);
                    ffma2(h1, bza, w[(2 * r) * 2 + 1]);
                    ffma2(h0, bzb, w[(2 * r + 1) * 2]);
                    ffma2(h1, bzb, w[(2 * r + 1) * 2 + 1]);
                }
                h[m * 2] = h0; h[m * 2 + 1] = h1;
            }
            #pragma unroll
            for (int c = 0; c < 8; ++c) { ulonglong2 u = wq[8 + c]; w[2*c] = u.x; w[2*c+1] = u.y; }
            #pragma unroll
            for (int m = 0; m < 4; ++m) {
                float ha, hb, hc, hd;
                unpack2(h[m * 2], ha, hb); unpack2(h[m * 2 + 1], hc, hd);
                ha = fmaxf(ha, 0.f); hb = fmaxf(hb, 0.f);
                hc = fmaxf(hc, 0.f); hd = fmaxf(hd, 0.f);
                ull d0 = pack2(ha, ha), d1 = pack2(hb, hb);
                ull d2 = pack2(hc, hc), d3 = pack2(hd, hd);
                #pragma unroll
                for (int q = 0; q < 4; ++q) {
                    ull acc = y[m * 4 + q];
                    ffma2(acc, d0, w[q]);
                    ffma2(acc, d1, w[4 + q]);
                    ffma2(acc, d2, w[8 + q]);
                    ffma2(acc, d3, w[12 + q]);
                    y[m * 4 + q] = acc;
                }
            }
        }
        #pragma unroll
        for (int m = 0; m < 4; ++m) {
            int n = nb + (m << 8);
            if (n < NNODES) {
                B3v[n] = y[m * 4 + 3];
                B2v[n] = y[m * 4 + 2];
                B1v[n] = y[m * 4 + 1];
                B0[n]  = add2(z[m * 4], add2(y[m * 4], b2p));
            }
        }
    }
    __syncthreads();

    // ---- layer-2 Horner: B2+=A*B3; B1+=A*B2; B0+=A*B1 ----
    propagate(B3v, B2v, meta, ssrc, true, tid); __syncthreads();
    propagate(B2v, B1v, meta, ssrc, true, tid); __syncthreads();
    propagate(B1v, B0,  meta, ssrc, true, tid); __syncthreads();

    ulonglong2* og2 = (ulonglong2*)(out + (size_t)g * (2 * NNODES));
    const ulonglong2* B0c = (const ulonglong2*)B0;
    for (int i = tid; i < NNODES / 2; i += TPB) og2[i] = B0c[i];
}

// ======================= host launch =========================================

extern "C" void kernel_launch(void* const* d_in, const int* in_sizes, int n_in,
                              void* d_out, int out_size) {
    const float* x   = (const float*)d_in[0];
    const int*   row = (const int*)d_in[1];
    const int*   col = (const int*)d_in[2];
    const float* ew  = (const float*)d_in[3];
    const float* W1  = (const float*)d_in[4];
    const float* b1  = (const float*)d_in[5];
    const float* W2  = (const float*)d_in[6];
    const float* b2  = (const float*)d_in[7];
    float* out = (float*)d_out;

    int E = in_sizes[1];
    int G = out_size / (2 * NNODES);

    cudaFuncSetAttribute(k_build, cudaFuncAttributeMaxDynamicSharedMemorySize, BUILD_SMEM);
    cudaFuncSetAttribute(k6_main, cudaFuncAttributeMaxDynamicSharedMemorySize, SM_TOTAL);

    k_build<<<1, BTPB, BUILD_SMEM>>>(row, col, ew, E);
    k6_main<<<G, TPB, SM_TOTAL>>>(x, W1, b1, W2, b2, out);
}